// round 13
// baseline (speedup 1.0000x reference)
#include <cuda_runtime.h>
#include <math.h>
#include <float.h>

#define B    64
#define P    196
#define ENC  2048
#define H    512
#define E    512
#define A_DIM 512
#define V    30000
#define T    20

#define NS_HC    8   // h0/c0 split-K (chunk 256 over K=2048)
#define NS_AG    16  // combined att_h+gate split-K (chunk 32 over K=512)
#define NS_GATES 24  // gates split-K (chunk 128 over K=3072)
#define GATE_OFF (NS_AG * B * A_DIM)   // gate partials region in g_part
#define MSAVE    1280                  // padded rows for batched pred ( >= 19*64 )

// ---------------- scratch (device globals, no allocations) ----------------
__device__ __align__(128) float g_att_enc[B * P * A_DIM];
__device__ __align__(128) float g_part[NS_GATES * B * 4 * H];
__device__ __align__(128) float g_mean[B * ENC];
__device__ __align__(128) float g_h[B * H];
__device__ __align__(128) float g_c[B * H];
__device__ __align__(128) float g_alpha[B * P];
__device__ __align__(128) float g_inp[B * (E + ENC)];
__device__ __align__(128) float g_hsave[MSAVE * H];   // h_t stacked, row = t*64+b

__device__ __forceinline__ float sigm(float x) { return 1.f / (1.f + expf(-x)); }

// =====================================================================
// gemm64: C(part)[M=64, Ntile=64], 128 thr, 8x4 microtile, BK=16,
// register-prefetch pipelined.
// MODE 0 plain, 2 dual-region K, 3 combined att_h+gate, 4 combined h0/c0.
// =====================================================================
template <int MODE>
__global__ void __launch_bounds__(128) gemm64_k(
    const float* __restrict__ A1, int lda1,
    const float* __restrict__ A2, int lda2,
    const float* __restrict__ W1, int ldw1,
    const float* __restrict__ W2, int ldw2, int K1,
    const float* __restrict__ bias,
    float* __restrict__ C, long long ldc, int N, int kchunk)
{
    __shared__ float As[16][64];
    __shared__ float Ws[16][64];
    const int tid = threadIdx.x;
    const int s   = blockIdx.y;
    const int k0b = s * kchunk;

    const float* Abase; int ldA;
    const float* Wbase; int ldW;
    float* Cb; long long ldcl; int Nloc;
    bool sigA = false;
    int n0;

    if (MODE == 3) {
        const bool isg = blockIdx.x >= (A_DIM / 64);
        sigA = isg;
        Nloc = isg ? ENC : A_DIM;
        Abase = A1 + k0b; ldA = lda1;
        Wbase = (isg ? W2 : W1) + k0b; ldW = ldw1;
        Cb = C + (isg ? (size_t)GATE_OFF + (size_t)s * 64 * ENC
                      : (size_t)s * 64 * A_DIM);
        ldcl = Nloc;
        n0 = (isg ? (blockIdx.x - A_DIM / 64) : blockIdx.x) * 64;
    } else if (MODE == 4) {
        // dual h0/c0: grid.x 0..7 -> Wch (h half), 8..15 -> Wcc (c half)
        const bool isc = blockIdx.x >= (H / 64);
        Nloc = H;
        Abase = A1 + k0b; ldA = lda1;
        Wbase = (isc ? W2 : W1) + k0b; ldW = ldw1;
        Cb = C + (size_t)s * 64 * (2 * H) + (isc ? H : 0);
        ldcl = 2 * H;
        n0 = (isc ? (blockIdx.x - H / 64) : blockIdx.x) * 64;
    } else {
        Nloc = N;
        if (MODE == 2 && k0b >= K1) { Abase = A2 + (k0b - K1); ldA = lda2; Wbase = W2 + (k0b - K1); ldW = ldw2; }
        else                        { Abase = A1 + k0b;        ldA = lda1; Wbase = W1 + k0b;        ldW = ldw1; }
        Cb = C + (size_t)s * 64 * ldc;
        ldcl = ldc;
        n0 = blockIdx.x * 64;
    }

    const int lr = tid & 63;
    const int lk = (tid >> 6) * 8;
    const int wrow = n0 + lr;
    const float* Ap = Abase + (size_t)lr * ldA + lk;
    const float* Wp = (wrow < Nloc) ? (Wbase + (size_t)wrow * ldW + lk) : nullptr;
    const int tx = tid & 15;
    const int ty = tid >> 4;

    float acc[8][4];
#pragma unroll
    for (int i = 0; i < 8; i++)
#pragma unroll
        for (int j = 0; j < 4; j++) acc[i][j] = 0.f;

    float4 a0 = *(const float4*)(Ap);
    float4 a1 = *(const float4*)(Ap + 4);
    float4 w0, w1;
    if (Wp) { w0 = *(const float4*)(Wp); w1 = *(const float4*)(Wp + 4); }
    else    { w0 = make_float4(0, 0, 0, 0); w1 = w0; }

    for (int kk0 = 0; kk0 < kchunk; kk0 += 16) {
        float4 sa0 = a0, sa1 = a1, sw0 = w0, sw1 = w1;
        if (MODE == 3 && sigA) {
            sa0.x = sigm(sa0.x); sa0.y = sigm(sa0.y); sa0.z = sigm(sa0.z); sa0.w = sigm(sa0.w);
            sa1.x = sigm(sa1.x); sa1.y = sigm(sa1.y); sa1.z = sigm(sa1.z); sa1.w = sigm(sa1.w);
        }
        __syncthreads();
        As[lk + 0][lr] = sa0.x; As[lk + 1][lr] = sa0.y; As[lk + 2][lr] = sa0.z; As[lk + 3][lr] = sa0.w;
        As[lk + 4][lr] = sa1.x; As[lk + 5][lr] = sa1.y; As[lk + 6][lr] = sa1.z; As[lk + 7][lr] = sa1.w;
        Ws[lk + 0][lr] = sw0.x; Ws[lk + 1][lr] = sw0.y; Ws[lk + 2][lr] = sw0.z; Ws[lk + 3][lr] = sw0.w;
        Ws[lk + 4][lr] = sw1.x; Ws[lk + 5][lr] = sw1.y; Ws[lk + 6][lr] = sw1.z; Ws[lk + 7][lr] = sw1.w;
        __syncthreads();

        if (kk0 + 16 < kchunk) {
            a0 = *(const float4*)(Ap + kk0 + 16);
            a1 = *(const float4*)(Ap + kk0 + 20);
            if (Wp) { w0 = *(const float4*)(Wp + kk0 + 16); w1 = *(const float4*)(Wp + kk0 + 20); }
        }

#pragma unroll
        for (int kk = 0; kk < 16; kk++) {
            float4 ra0 = *(const float4*)&As[kk][ty * 8];
            float4 ra1 = *(const float4*)&As[kk][ty * 8 + 4];
            float4 rw  = *(const float4*)&Ws[kk][tx * 4];
            acc[0][0] += ra0.x * rw.x; acc[0][1] += ra0.x * rw.y; acc[0][2] += ra0.x * rw.z; acc[0][3] += ra0.x * rw.w;
            acc[1][0] += ra0.y * rw.x; acc[1][1] += ra0.y * rw.y; acc[1][2] += ra0.y * rw.z; acc[1][3] += ra0.y * rw.w;
            acc[2][0] += ra0.z * rw.x; acc[2][1] += ra0.z * rw.y; acc[2][2] += ra0.z * rw.z; acc[2][3] += ra0.z * rw.w;
            acc[3][0] += ra0.w * rw.x; acc[3][1] += ra0.w * rw.y; acc[3][2] += ra0.w * rw.z; acc[3][3] += ra0.w * rw.w;
            acc[4][0] += ra1.x * rw.x; acc[4][1] += ra1.x * rw.y; acc[4][2] += ra1.x * rw.z; acc[4][3] += ra1.x * rw.w;
            acc[5][0] += ra1.y * rw.x; acc[5][1] += ra1.y * rw.y; acc[5][2] += ra1.y * rw.z; acc[5][3] += ra1.y * rw.w;
            acc[6][0] += ra1.z * rw.x; acc[6][1] += ra1.z * rw.y; acc[6][2] += ra1.z * rw.z; acc[6][3] += ra1.z * rw.w;
            acc[7][0] += ra1.w * rw.x; acc[7][1] += ra1.w * rw.y; acc[7][2] += ra1.w * rw.z; acc[7][3] += ra1.w * rw.w;
        }
    }

#pragma unroll
    for (int i = 0; i < 8; i++) {
        const int mm = ty * 8 + i;
        const int n  = n0 + tx * 4;
        if (n < Nloc) {
            float4 v = make_float4(acc[i][0], acc[i][1], acc[i][2], acc[i][3]);
            if (MODE == 0 && bias) {
                const float4 bv = *(const float4*)(bias + n);
                v.x += bv.x; v.y += bv.y; v.z += bv.z; v.w += bv.w;
            }
            *(float4*)(Cb + (size_t)mm * ldcl + n) = v;
        }
    }
}

// =====================================================================
// gemm_big: 128x128 tile, 256 thr, 8x8 microtile, pipelined — att_enc.
// =====================================================================
__global__ void __launch_bounds__(256) gemm_big_k(
    const float* __restrict__ Am,
    const float* __restrict__ Wm,
    const float* __restrict__ bias,
    float* __restrict__ C)
{
    __shared__ float As[16][128];
    __shared__ float Ws[16][128];
    const int tid = threadIdx.x;
    const int n0 = blockIdx.x * 128;
    const int m0 = blockIdx.y * 128;
    const int lr = tid & 127;
    const int lk = (tid >> 7) * 8;
    const float* Ap = Am + (size_t)(m0 + lr) * ENC + lk;
    const float* Wp = Wm + (size_t)(n0 + lr) * ENC + lk;
    const int tx = tid & 15;
    const int ty = tid >> 4;

    float acc[8][8];
#pragma unroll
    for (int i = 0; i < 8; i++)
#pragma unroll
        for (int j = 0; j < 8; j++) acc[i][j] = 0.f;

    float4 a0 = *(const float4*)(Ap);
    float4 a1 = *(const float4*)(Ap + 4);
    float4 w0 = *(const float4*)(Wp);
    float4 w1 = *(const float4*)(Wp + 4);

    for (int k0 = 0; k0 < ENC; k0 += 16) {
        __syncthreads();
        As[lk + 0][lr] = a0.x; As[lk + 1][lr] = a0.y; As[lk + 2][lr] = a0.z; As[lk + 3][lr] = a0.w;
        As[lk + 4][lr] = a1.x; As[lk + 5][lr] = a1.y; As[lk + 6][lr] = a1.z; As[lk + 7][lr] = a1.w;
        Ws[lk + 0][lr] = w0.x; Ws[lk + 1][lr] = w0.y; Ws[lk + 2][lr] = w0.z; Ws[lk + 3][lr] = w0.w;
        Ws[lk + 4][lr] = w1.x; Ws[lk + 5][lr] = w1.y; Ws[lk + 6][lr] = w1.z; Ws[lk + 7][lr] = w1.w;
        __syncthreads();

        if (k0 + 16 < ENC) {
            a0 = *(const float4*)(Ap + k0 + 16);
            a1 = *(const float4*)(Ap + k0 + 20);
            w0 = *(const float4*)(Wp + k0 + 16);
            w1 = *(const float4*)(Wp + k0 + 20);
        }

#pragma unroll
        for (int kk = 0; kk < 16; kk++) {
            float4 ra0 = *(const float4*)&As[kk][ty * 8];
            float4 ra1 = *(const float4*)&As[kk][ty * 8 + 4];
            float4 rw0 = *(const float4*)&Ws[kk][tx * 8];
            float4 rw1 = *(const float4*)&Ws[kk][tx * 8 + 4];
            const float aval[8] = {ra0.x, ra0.y, ra0.z, ra0.w, ra1.x, ra1.y, ra1.z, ra1.w};
            const float wval[8] = {rw0.x, rw0.y, rw0.z, rw0.w, rw1.x, rw1.y, rw1.z, rw1.w};
#pragma unroll
            for (int i = 0; i < 8; i++)
#pragma unroll
                for (int j = 0; j < 8; j++) acc[i][j] += aval[i] * wval[j];
        }
    }

#pragma unroll
    for (int i = 0; i < 8; i++) {
        const int m = m0 + ty * 8 + i;
#pragma unroll
        for (int jj = 0; jj < 2; jj++) {
            const int n = n0 + tx * 8 + jj * 4;
            const float4 bv = *(const float4*)(bias + n);
            float4 v = make_float4(acc[i][jj*4+0] + bv.x, acc[i][jj*4+1] + bv.y,
                                   acc[i][jj*4+2] + bv.z, acc[i][jj*4+3] + bv.w);
            *(float4*)(C + (size_t)m * A_DIM + n) = v;
        }
    }
}

// =====================================================================
// pred_big: batched vocab projection for ALL timesteps in one GEMM.
// =====================================================================
__global__ void __launch_bounds__(256) pred_big_k(
    const float* __restrict__ Wfc,
    const float* __restrict__ bfc,
    float* __restrict__ out)
{
    __shared__ float As[16][128];
    __shared__ float Ws[16][128];
    const int tid = threadIdx.x;
    const int n0 = blockIdx.x * 128;
    const int m0 = blockIdx.y * 128;
    const int lr = tid & 127;
    const int lk = (tid >> 7) * 8;
    const float* Ap = g_hsave + (size_t)(m0 + lr) * H + lk;
    const int wr = min(n0 + lr, V - 1);
    const float* Wp = Wfc + (size_t)wr * H + lk;
    const int tx = tid & 15;
    const int ty = tid >> 4;

    float acc[8][8];
#pragma unroll
    for (int i = 0; i < 8; i++)
#pragma unroll
        for (int j = 0; j < 8; j++) acc[i][j] = 0.f;

    float4 a0 = *(const float4*)(Ap);
    float4 a1 = *(const float4*)(Ap + 4);
    float4 w0 = *(const float4*)(Wp);
    float4 w1 = *(const float4*)(Wp + 4);

    for (int k0 = 0; k0 < H; k0 += 16) {
        __syncthreads();
        As[lk + 0][lr] = a0.x; As[lk + 1][lr] = a0.y; As[lk + 2][lr] = a0.z; As[lk + 3][lr] = a0.w;
        As[lk + 4][lr] = a1.x; As[lk + 5][lr] = a1.y; As[lk + 6][lr] = a1.z; As[lk + 7][lr] = a1.w;
        Ws[lk + 0][lr] = w0.x; Ws[lk + 1][lr] = w0.y; Ws[lk + 2][lr] = w0.z; Ws[lk + 3][lr] = w0.w;
        Ws[lk + 4][lr] = w1.x; Ws[lk + 5][lr] = w1.y; Ws[lk + 6][lr] = w1.z; Ws[lk + 7][lr] = w1.w;
        __syncthreads();

        if (k0 + 16 < H) {
            a0 = *(const float4*)(Ap + k0 + 16);
            a1 = *(const float4*)(Ap + k0 + 20);
            w0 = *(const float4*)(Wp + k0 + 16);
            w1 = *(const float4*)(Wp + k0 + 20);
        }

#pragma unroll
        for (int kk = 0; kk < 16; kk++) {
            float4 ra0 = *(const float4*)&As[kk][ty * 8];
            float4 ra1 = *(const float4*)&As[kk][ty * 8 + 4];
            float4 rw0 = *(const float4*)&Ws[kk][tx * 8];
            float4 rw1 = *(const float4*)&Ws[kk][tx * 8 + 4];
            const float aval[8] = {ra0.x, ra0.y, ra0.z, ra0.w, ra1.x, ra1.y, ra1.z, ra1.w};
            const float wval[8] = {rw0.x, rw0.y, rw0.z, rw0.w, rw1.x, rw1.y, rw1.z, rw1.w};
#pragma unroll
            for (int i = 0; i < 8; i++)
#pragma unroll
                for (int j = 0; j < 8; j++) acc[i][j] += aval[i] * wval[j];
        }
    }

#pragma unroll
    for (int i = 0; i < 8; i++) {
        const int r = m0 + ty * 8 + i;              // = t*64 + b
        if (r < (T - 1) * B) {
            const int t = r >> 6;
            const int b = r & 63;
            float* orow = out + (size_t)b * T * V + (size_t)t * V;
#pragma unroll
            for (int jj = 0; jj < 2; jj++) {
                const int n = n0 + tx * 8 + jj * 4;
                if (n < V) {
                    const float4 bv = *(const float4*)(bfc + n);
                    float4 v = make_float4(acc[i][jj*4+0] + bv.x, acc[i][jj*4+1] + bv.y,
                                           acc[i][jj*4+2] + bv.z, acc[i][jj*4+3] + bv.w);
                    *(float4*)(orow + n) = v;
                }
            }
        }
    }
}

// ---------------- mean over P (float4 vectorized) ----------------
__global__ void mean_k(const float* __restrict__ enc)
{
    const int idx = blockIdx.x * 256 + threadIdx.x;   // over B*ENC/4
    const int b = idx / (ENC / 4);
    const int e4 = idx - b * (ENC / 4);
    const float4* p = (const float4*)(enc + (size_t)b * P * ENC) + e4;
    float4 s = make_float4(0.f, 0.f, 0.f, 0.f);
    for (int pp = 0; pp < P; pp++) {
        const float4 v = p[(size_t)pp * (ENC / 4)];
        s.x += v.x; s.y += v.y; s.z += v.z; s.w += v.w;
    }
    const float r = 1.f / (float)P;
    s.x *= r; s.y *= r; s.z *= r; s.w *= r;
    ((float4*)g_mean)[idx] = s;
}

// ---------------- reduce dual h0/c0 partials ----------------
__global__ void reduce_hc_k(const float* __restrict__ bch, const float* __restrict__ bcc)
{
    const int idx = blockIdx.x * 256 + threadIdx.x;   // B*2H
    const int b = idx / (2 * H);
    const int n = idx - b * (2 * H);
    float s = (n < H) ? bch[n] : bcc[n - H];
    for (int ss = 0; ss < NS_HC; ss++) s += g_part[(size_t)(ss * 64 + b) * (2 * H) + n];
    if (n < H) g_h[b * H + n] = s;
    else       g_c[b * H + (n - H)] = s;
}

// ---------------- fused: att_h partial-reduce + scores + softmax ----------
__global__ void __launch_bounds__(256) scores_k(
    const float* __restrict__ bh, const float* __restrict__ Wa, const float* __restrict__ ba)
{
    __shared__ float sh_h[A_DIM];
    __shared__ float sh_w[A_DIM];
    __shared__ float sc[256];
    __shared__ float red[256];
    const int b = blockIdx.x;
    const int tid = threadIdx.x;
    for (int a = tid; a < A_DIM; a += 256) {
        float s = bh[a];
#pragma unroll
        for (int ss = 0; ss < NS_AG; ss++) s += g_part[(size_t)(ss * 64 + b) * A_DIM + a];
        sh_h[a] = s;
        sh_w[a] = Wa[a];
    }
    __syncthreads();
    const int w = tid >> 5, lane = tid & 31;
    for (int p = w; p < P; p += 8) {
        const float* row = g_att_enc + (size_t)(b * P + p) * A_DIM;
        float s = 0.f;
#pragma unroll 4
        for (int a = lane; a < A_DIM; a += 32) {
            const float v = row[a] + sh_h[a];
            s += fmaxf(v, 0.f) * sh_w[a];
        }
#pragma unroll
        for (int off = 16; off; off >>= 1) s += __shfl_xor_sync(0xffffffff, s, off);
        if (lane == 0) sc[p] = s + ba[0];
    }
    __syncthreads();
    const float v = (tid < P) ? sc[tid] : -FLT_MAX;
    red[tid] = v;
    __syncthreads();
    for (int off = 128; off; off >>= 1) { if (tid < off) red[tid] = fmaxf(red[tid], red[tid + off]); __syncthreads(); }
    const float mx = red[0];
    __syncthreads();
    const float e = (tid < P) ? expf(v - mx) : 0.f;
    red[tid] = e;
    __syncthreads();
    for (int off = 128; off; off >>= 1) { if (tid < off) red[tid] += red[tid + off]; __syncthreads(); }
    const float inv = 1.f / red[0];
    if (tid < P) g_alpha[b * P + tid] = e * inv;
}

// =====================================================================
// mkinp: merged weighted-sum + gate-reduce + inp build + emb gather.
// =====================================================================
__global__ void __launch_bounds__(256) mkinp_k(
    const float* __restrict__ enc,
    const float* __restrict__ emb, const int* __restrict__ cap,
    const float* __restrict__ bg, int t)
{
    __shared__ float sa[P];
    const int idx = blockIdx.x * 256 + threadIdx.x;
    const int b = idx / (E + ENC);
    const int j = idx - b * (E + ENC);

    if (threadIdx.x < P) sa[threadIdx.x] = g_alpha[b * P + threadIdx.x];
    __syncthreads();

    if (j < E) {
        const int tok = cap[b * T + t];
        g_inp[idx] = emb[(size_t)tok * E + j];
    } else {
        const int ee = j - E;
        const float* col = enc + (size_t)b * P * ENC + ee;
        float s = 0.f;
#pragma unroll 4
        for (int p = 0; p < P; p++) s += sa[p] * col[(size_t)p * ENC];
        float g = bg[ee];
#pragma unroll
        for (int ss = 0; ss < NS_AG; ss++) g += g_part[GATE_OFF + (size_t)(ss * 64 + b) * ENC + ee];
        g_inp[idx] = s * g;
    }
}

// ---------------- LSTM cell (also appends h_t to g_hsave) ------------------
__global__ void lstm_k(const float* __restrict__ b_ih, const float* __restrict__ b_hh, int t)
{
    const int idx = blockIdx.x * 256 + threadIdx.x;
    const int b = idx >> 9;
    const int n = idx & (H - 1);
    float gv[4];
#pragma unroll
    for (int q = 0; q < 4; q++) {
        const int pos = q * H + n;
        float s = b_ih[pos] + b_hh[pos];
#pragma unroll
        for (int ss = 0; ss < NS_GATES; ss++) s += g_part[(size_t)(ss * 64 + b) * (4 * H) + pos];
        gv[q] = s;
    }
    const float i_ = sigm(gv[0]);
    const float f_ = sigm(gv[1]);
    const float gg = tanhf(gv[2]);
    const float o_ = sigm(gv[3]);
    const float c  = f_ * g_c[idx] + i_ * gg;
    g_c[idx] = c;
    const float hv = o_ * tanhf(c);
    g_h[idx] = hv;
    g_hsave[(size_t)t * (B * H) + idx] = hv;
}

// ---------------- zero the final time step ----------------
__global__ void zero_k(float* __restrict__ out)
{
    const int idx = blockIdx.x * 256 + threadIdx.x;
    if (idx < B * V) {
        const int b = idx / V;
        const int n = idx - b * V;
        out[(size_t)b * T * V + (size_t)(T - 1) * V + n] = 0.f;
    }
}

// ---------------- launch ----------------
extern "C" void kernel_launch(void* const* d_in, const int* in_sizes, int n_in,
                              void* d_out, int out_size)
{
    const float* enc  = (const float*)d_in[0];
    const int*   cap  = (const int*)d_in[1];
    const float* emb  = (const float*)d_in[2];
    const float* W_ih = (const float*)d_in[3];
    const float* b_ih = (const float*)d_in[4];
    const float* W_hh = (const float*)d_in[5];
    const float* b_hh = (const float*)d_in[6];
    const float* We   = (const float*)d_in[7];
    const float* be   = (const float*)d_in[8];
    const float* Wh   = (const float*)d_in[9];
    const float* bh   = (const float*)d_in[10];
    const float* Wa   = (const float*)d_in[11];
    const float* ba   = (const float*)d_in[12];
    const float* Wch  = (const float*)d_in[13];
    const float* bch  = (const float*)d_in[14];
    const float* Wcc  = (const float*)d_in[15];
    const float* bcc  = (const float*)d_in[16];
    const float* Wfc  = (const float*)d_in[17];
    const float* bfc  = (const float*)d_in[18];
    const float* Wg   = (const float*)d_in[19];
    const float* bg   = (const float*)d_in[20];
    float* out = (float*)d_out;

    float *p_att_enc, *p_part, *p_mean, *p_h, *p_c, *p_inp;
    cudaGetSymbolAddress((void**)&p_att_enc, g_att_enc);
    cudaGetSymbolAddress((void**)&p_part,    g_part);
    cudaGetSymbolAddress((void**)&p_mean,    g_mean);
    cudaGetSymbolAddress((void**)&p_h,       g_h);
    cudaGetSymbolAddress((void**)&p_c,       g_c);
    cudaGetSymbolAddress((void**)&p_inp,     g_inp);

    // ---- setup ----
    mean_k<<<(B * ENC / 4) / 256, 256>>>(enc);
    // h0 AND c0 in one dual-weight GEMM (grid 16 x 8), then one reduce
    gemm64_k<4><<<dim3(2 * H / 64, NS_HC), 128>>>(p_mean, ENC, nullptr, 0, Wch, ENC, Wcc, ENC, 0,
                                                  nullptr, p_part, 0, 0, ENC / NS_HC);
    reduce_hc_k<<<(B * 2 * H) / 256, 256>>>(bch, bcc);
    // att_enc = encode_out @ We^T + be   (grid 4 x 98, pipelined)
    gemm_big_k<<<dim3(A_DIM / 128, (B * P) / 128), 256>>>(enc, We, be, p_att_enc);

    // ---- recurrent loop: 5 launches per step ----
    for (int t = 0; t < T - 1; t++) {
        // att_h (h @ Wh^T) + gate (sigmoid(h) @ Wg^T) partials, split-K 16
        gemm64_k<3><<<dim3((A_DIM + ENC) / 64, NS_AG), 128>>>(
            p_h, H, nullptr, 0, Wh, H, Wg, H, 0, nullptr, p_part, 0, 0, H / NS_AG);
        // att_h reduce + scores + softmax -> alpha
        scores_k<<<B, 256>>>(bh, Wa, ba);
        // weighted + gate + inp build + emb gather
        mkinp_k<<<(B * (E + ENC)) / 256, 256>>>(enc, emb, cap, bg, t);
        // gates partials: dual-region K=3072, split-K 24 (chunk 128; boundary at block 20)
        gemm64_k<2><<<dim3((4 * H) / 64, NS_GATES), 128>>>(p_inp, E + ENC, p_h, H,
                                                           W_ih, E + ENC, W_hh, H, E + ENC,
                                                           nullptr, p_part, 4 * H, 4 * H, (E + ENC + H) / NS_GATES);
        lstm_k<<<(B * H) / 256, 256>>>(b_ih, b_hh, t);
    }

    // ---- ONE batched vocab projection for all 19 steps ----
    pred_big_k<<<dim3((V + 127) / 128, MSAVE / 128), 256>>>(Wfc, bfc, out);

    // out[:, T-1, :] = 0
    zero_k<<<(B * V + 255) / 256, 256>>>(out);
}

// round 15
// speedup vs baseline: 1.0856x; 1.0856x over previous
#include <cuda_runtime.h>
#include <math.h>
#include <float.h>

#define B    64
#define P    196
#define ENC  2048
#define H    512
#define E    512
#define A_DIM 512
#define V    30000
#define T    20

#define NS_HC    8   // h0/c0 split-K (chunk 256 over K=2048)
#define NS_AG    8   // combined att_h+gate split-K (chunk 64 over K=512)
#define NS_GATES 12  // gates split-K (chunk 256 over K=3072)
#define GATE_OFF (NS_AG * B * A_DIM)   // gate partials region in g_part
#define MSAVE    1280                  // padded rows for batched pred ( >= 19*64 )

// ---------------- scratch (device globals, no allocations) ----------------
__device__ __align__(128) float g_att_enc[B * P * A_DIM];
__device__ __align__(128) float g_part[NS_GATES * B * 4 * H];
__device__ __align__(128) float g_mean[B * ENC];
__device__ __align__(128) float g_h[B * H];
__device__ __align__(128) float g_c[B * H];
__device__ __align__(128) float g_alpha[B * P];
__device__ __align__(128) float g_inp[B * (E + ENC)];
__device__ __align__(128) float g_hsave[MSAVE * H];   // h_t stacked, row = t*64+b

__device__ __forceinline__ float sigm(float x) { return 1.f / (1.f + expf(-x)); }

// =====================================================================
// gemm64: C(part)[M=64, Ntile=64], 128 thr, 8x4 microtile, BK=16,
// register-prefetch pipelined.
// MODE 0 plain, 2 dual-region K, 3 combined att_h+gate, 4 combined h0/c0.
// =====================================================================
template <int MODE>
__global__ void __launch_bounds__(128) gemm64_k(
    const float* __restrict__ A1, int lda1,
    const float* __restrict__ A2, int lda2,
    const float* __restrict__ W1, int ldw1,
    const float* __restrict__ W2, int ldw2, int K1,
    const float* __restrict__ bias,
    float* __restrict__ C, long long ldc, int N, int kchunk)
{
    __shared__ float As[16][64];
    __shared__ float Ws[16][64];
    const int tid = threadIdx.x;
    const int s   = blockIdx.y;
    const int k0b = s * kchunk;

    const float* Abase; int ldA;
    const float* Wbase; int ldW;
    float* Cb; long long ldcl; int Nloc;
    bool sigA = false;
    int n0;

    if (MODE == 3) {
        const bool isg = blockIdx.x >= (A_DIM / 64);
        sigA = isg;
        Nloc = isg ? ENC : A_DIM;
        Abase = A1 + k0b; ldA = lda1;
        Wbase = (isg ? W2 : W1) + k0b; ldW = ldw1;
        Cb = C + (isg ? (size_t)GATE_OFF + (size_t)s * 64 * ENC
                      : (size_t)s * 64 * A_DIM);
        ldcl = Nloc;
        n0 = (isg ? (blockIdx.x - A_DIM / 64) : blockIdx.x) * 64;
    } else if (MODE == 4) {
        const bool isc = blockIdx.x >= (H / 64);
        Nloc = H;
        Abase = A1 + k0b; ldA = lda1;
        Wbase = (isc ? W2 : W1) + k0b; ldW = ldw1;
        Cb = C + (size_t)s * 64 * (2 * H) + (isc ? H : 0);
        ldcl = 2 * H;
        n0 = (isc ? (blockIdx.x - H / 64) : blockIdx.x) * 64;
    } else {
        Nloc = N;
        if (MODE == 2 && k0b >= K1) { Abase = A2 + (k0b - K1); ldA = lda2; Wbase = W2 + (k0b - K1); ldW = ldw2; }
        else                        { Abase = A1 + k0b;        ldA = lda1; Wbase = W1 + k0b;        ldW = ldw1; }
        Cb = C + (size_t)s * 64 * ldc;
        ldcl = ldc;
        n0 = blockIdx.x * 64;
    }

    const int lr = tid & 63;
    const int lk = (tid >> 6) * 8;
    const int wrow = n0 + lr;
    const float* Ap = Abase + (size_t)lr * ldA + lk;
    const float* Wp = (wrow < Nloc) ? (Wbase + (size_t)wrow * ldW + lk) : nullptr;
    const int tx = tid & 15;
    const int ty = tid >> 4;

    float acc[8][4];
#pragma unroll
    for (int i = 0; i < 8; i++)
#pragma unroll
        for (int j = 0; j < 4; j++) acc[i][j] = 0.f;

    float4 a0 = *(const float4*)(Ap);
    float4 a1 = *(const float4*)(Ap + 4);
    float4 w0, w1;
    if (Wp) { w0 = *(const float4*)(Wp); w1 = *(const float4*)(Wp + 4); }
    else    { w0 = make_float4(0, 0, 0, 0); w1 = w0; }

    for (int kk0 = 0; kk0 < kchunk; kk0 += 16) {
        float4 sa0 = a0, sa1 = a1, sw0 = w0, sw1 = w1;
        if (MODE == 3 && sigA) {
            sa0.x = sigm(sa0.x); sa0.y = sigm(sa0.y); sa0.z = sigm(sa0.z); sa0.w = sigm(sa0.w);
            sa1.x = sigm(sa1.x); sa1.y = sigm(sa1.y); sa1.z = sigm(sa1.z); sa1.w = sigm(sa1.w);
        }
        __syncthreads();
        As[lk + 0][lr] = sa0.x; As[lk + 1][lr] = sa0.y; As[lk + 2][lr] = sa0.z; As[lk + 3][lr] = sa0.w;
        As[lk + 4][lr] = sa1.x; As[lk + 5][lr] = sa1.y; As[lk + 6][lr] = sa1.z; As[lk + 7][lr] = sa1.w;
        Ws[lk + 0][lr] = sw0.x; Ws[lk + 1][lr] = sw0.y; Ws[lk + 2][lr] = sw0.z; Ws[lk + 3][lr] = sw0.w;
        Ws[lk + 4][lr] = sw1.x; Ws[lk + 5][lr] = sw1.y; Ws[lk + 6][lr] = sw1.z; Ws[lk + 7][lr] = sw1.w;
        __syncthreads();

        if (kk0 + 16 < kchunk) {
            a0 = *(const float4*)(Ap + kk0 + 16);
            a1 = *(const float4*)(Ap + kk0 + 20);
            if (Wp) { w0 = *(const float4*)(Wp + kk0 + 16); w1 = *(const float4*)(Wp + kk0 + 20); }
        }

#pragma unroll
        for (int kk = 0; kk < 16; kk++) {
            float4 ra0 = *(const float4*)&As[kk][ty * 8];
            float4 ra1 = *(const float4*)&As[kk][ty * 8 + 4];
            float4 rw  = *(const float4*)&Ws[kk][tx * 4];
            acc[0][0] += ra0.x * rw.x; acc[0][1] += ra0.x * rw.y; acc[0][2] += ra0.x * rw.z; acc[0][3] += ra0.x * rw.w;
            acc[1][0] += ra0.y * rw.x; acc[1][1] += ra0.y * rw.y; acc[1][2] += ra0.y * rw.z; acc[1][3] += ra0.y * rw.w;
            acc[2][0] += ra0.z * rw.x; acc[2][1] += ra0.z * rw.y; acc[2][2] += ra0.z * rw.z; acc[2][3] += ra0.z * rw.w;
            acc[3][0] += ra0.w * rw.x; acc[3][1] += ra0.w * rw.y; acc[3][2] += ra0.w * rw.z; acc[3][3] += ra0.w * rw.w;
            acc[4][0] += ra1.x * rw.x; acc[4][1] += ra1.x * rw.y; acc[4][2] += ra1.x * rw.z; acc[4][3] += ra1.x * rw.w;
            acc[5][0] += ra1.y * rw.x; acc[5][1] += ra1.y * rw.y; acc[5][2] += ra1.y * rw.z; acc[5][3] += ra1.y * rw.w;
            acc[6][0] += ra1.z * rw.x; acc[6][1] += ra1.z * rw.y; acc[6][2] += ra1.z * rw.z; acc[6][3] += ra1.z * rw.w;
            acc[7][0] += ra1.w * rw.x; acc[7][1] += ra1.w * rw.y; acc[7][2] += ra1.w * rw.z; acc[7][3] += ra1.w * rw.w;
        }
    }

#pragma unroll
    for (int i = 0; i < 8; i++) {
        const int mm = ty * 8 + i;
        const int n  = n0 + tx * 4;
        if (n < Nloc) {
            float4 v = make_float4(acc[i][0], acc[i][1], acc[i][2], acc[i][3]);
            if (MODE == 0 && bias) {
                const float4 bv = *(const float4*)(bias + n);
                v.x += bv.x; v.y += bv.y; v.z += bv.z; v.w += bv.w;
            }
            *(float4*)(Cb + (size_t)mm * ldcl + n) = v;
        }
    }
}

// =====================================================================
// gemm_big: 128x128 tile, 256 thr, 8x8 microtile, pipelined — att_enc.
// Conflict-free W reads: thread columns are {tx*4..+3} and {64+tx*4..+3}.
// =====================================================================
__global__ void __launch_bounds__(256) gemm_big_k(
    const float* __restrict__ Am,
    const float* __restrict__ Wm,
    const float* __restrict__ bias,
    float* __restrict__ C)
{
    __shared__ float As[16][128];
    __shared__ float Ws[16][128];
    const int tid = threadIdx.x;
    const int n0 = blockIdx.x * 128;
    const int m0 = blockIdx.y * 128;
    const int lr = tid & 127;
    const int lk = (tid >> 7) * 8;
    const float* Ap = Am + (size_t)(m0 + lr) * ENC + lk;
    const float* Wp = Wm + (size_t)(n0 + lr) * ENC + lk;
    const int tx = tid & 15;
    const int ty = tid >> 4;

    float acc[8][8];
#pragma unroll
    for (int i = 0; i < 8; i++)
#pragma unroll
        for (int j = 0; j < 8; j++) acc[i][j] = 0.f;

    float4 a0 = *(const float4*)(Ap);
    float4 a1 = *(const float4*)(Ap + 4);
    float4 w0 = *(const float4*)(Wp);
    float4 w1 = *(const float4*)(Wp + 4);

    for (int k0 = 0; k0 < ENC; k0 += 16) {
        __syncthreads();
        As[lk + 0][lr] = a0.x; As[lk + 1][lr] = a0.y; As[lk + 2][lr] = a0.z; As[lk + 3][lr] = a0.w;
        As[lk + 4][lr] = a1.x; As[lk + 5][lr] = a1.y; As[lk + 6][lr] = a1.z; As[lk + 7][lr] = a1.w;
        Ws[lk + 0][lr] = w0.x; Ws[lk + 1][lr] = w0.y; Ws[lk + 2][lr] = w0.z; Ws[lk + 3][lr] = w0.w;
        Ws[lk + 4][lr] = w1.x; Ws[lk + 5][lr] = w1.y; Ws[lk + 6][lr] = w1.z; Ws[lk + 7][lr] = w1.w;
        __syncthreads();

        if (k0 + 16 < ENC) {
            a0 = *(const float4*)(Ap + k0 + 16);
            a1 = *(const float4*)(Ap + k0 + 20);
            w0 = *(const float4*)(Wp + k0 + 16);
            w1 = *(const float4*)(Wp + k0 + 20);
        }

#pragma unroll
        for (int kk = 0; kk < 16; kk++) {
            float4 ra0 = *(const float4*)&As[kk][ty * 8];
            float4 ra1 = *(const float4*)&As[kk][ty * 8 + 4];
            float4 rw0 = *(const float4*)&Ws[kk][tx * 4];        // cols tx*4..+3 (16B stride: conflict-free)
            float4 rw1 = *(const float4*)&Ws[kk][64 + tx * 4];   // cols 64+tx*4..+3
            const float aval[8] = {ra0.x, ra0.y, ra0.z, ra0.w, ra1.x, ra1.y, ra1.z, ra1.w};
            const float wval[8] = {rw0.x, rw0.y, rw0.z, rw0.w, rw1.x, rw1.y, rw1.z, rw1.w};
#pragma unroll
            for (int i = 0; i < 8; i++)
#pragma unroll
                for (int j = 0; j < 8; j++) acc[i][j] += aval[i] * wval[j];
        }
    }

#pragma unroll
    for (int i = 0; i < 8; i++) {
        const int m = m0 + ty * 8 + i;
#pragma unroll
        for (int jj = 0; jj < 2; jj++) {
            const int n = n0 + jj * 64 + tx * 4;
            const float4 bv = *(const float4*)(bias + n);
            float4 v = make_float4(acc[i][jj*4+0] + bv.x, acc[i][jj*4+1] + bv.y,
                                   acc[i][jj*4+2] + bv.z, acc[i][jj*4+3] + bv.w);
            *(float4*)(C + (size_t)m * A_DIM + n) = v;
        }
    }
}

// =====================================================================
// pred_big: batched vocab projection, conflict-free W reads (as above).
// =====================================================================
__global__ void __launch_bounds__(256) pred_big_k(
    const float* __restrict__ Wfc,
    const float* __restrict__ bfc,
    float* __restrict__ out)
{
    __shared__ float As[16][128];
    __shared__ float Ws[16][128];
    const int tid = threadIdx.x;
    const int n0 = blockIdx.x * 128;
    const int m0 = blockIdx.y * 128;
    const int lr = tid & 127;
    const int lk = (tid >> 7) * 8;
    const float* Ap = g_hsave + (size_t)(m0 + lr) * H + lk;
    const int wr = min(n0 + lr, V - 1);
    const float* Wp = Wfc + (size_t)wr * H + lk;
    const int tx = tid & 15;
    const int ty = tid >> 4;

    float acc[8][8];
#pragma unroll
    for (int i = 0; i < 8; i++)
#pragma unroll
        for (int j = 0; j < 8; j++) acc[i][j] = 0.f;

    float4 a0 = *(const float4*)(Ap);
    float4 a1 = *(const float4*)(Ap + 4);
    float4 w0 = *(const float4*)(Wp);
    float4 w1 = *(const float4*)(Wp + 4);

    for (int k0 = 0; k0 < H; k0 += 16) {
        __syncthreads();
        As[lk + 0][lr] = a0.x; As[lk + 1][lr] = a0.y; As[lk + 2][lr] = a0.z; As[lk + 3][lr] = a0.w;
        As[lk + 4][lr] = a1.x; As[lk + 5][lr] = a1.y; As[lk + 6][lr] = a1.z; As[lk + 7][lr] = a1.w;
        Ws[lk + 0][lr] = w0.x; Ws[lk + 1][lr] = w0.y; Ws[lk + 2][lr] = w0.z; Ws[lk + 3][lr] = w0.w;
        Ws[lk + 4][lr] = w1.x; Ws[lk + 5][lr] = w1.y; Ws[lk + 6][lr] = w1.z; Ws[lk + 7][lr] = w1.w;
        __syncthreads();

        if (k0 + 16 < H) {
            a0 = *(const float4*)(Ap + k0 + 16);
            a1 = *(const float4*)(Ap + k0 + 20);
            w0 = *(const float4*)(Wp + k0 + 16);
            w1 = *(const float4*)(Wp + k0 + 20);
        }

#pragma unroll
        for (int kk = 0; kk < 16; kk++) {
            float4 ra0 = *(const float4*)&As[kk][ty * 8];
            float4 ra1 = *(const float4*)&As[kk][ty * 8 + 4];
            float4 rw0 = *(const float4*)&Ws[kk][tx * 4];
            float4 rw1 = *(const float4*)&Ws[kk][64 + tx * 4];
            const float aval[8] = {ra0.x, ra0.y, ra0.z, ra0.w, ra1.x, ra1.y, ra1.z, ra1.w};
            const float wval[8] = {rw0.x, rw0.y, rw0.z, rw0.w, rw1.x, rw1.y, rw1.z, rw1.w};
#pragma unroll
            for (int i = 0; i < 8; i++)
#pragma unroll
                for (int j = 0; j < 8; j++) acc[i][j] += aval[i] * wval[j];
        }
    }

#pragma unroll
    for (int i = 0; i < 8; i++) {
        const int r = m0 + ty * 8 + i;              // = t*64 + b
        if (r < (T - 1) * B) {
            const int t = r >> 6;
            const int b = r & 63;
            float* orow = out + (size_t)b * T * V + (size_t)t * V;
#pragma unroll
            for (int jj = 0; jj < 2; jj++) {
                const int n = n0 + jj * 64 + tx * 4;
                if (n < V) {                        // V % 4 == 0
                    const float4 bv = *(const float4*)(bfc + n);
                    float4 v = make_float4(acc[i][jj*4+0] + bv.x, acc[i][jj*4+1] + bv.y,
                                           acc[i][jj*4+2] + bv.z, acc[i][jj*4+3] + bv.w);
                    *(float4*)(orow + n) = v;
                }
            }
        }
    }
}

// ---------------- mean over P (float4 vectorized) ----------------
__global__ void mean_k(const float* __restrict__ enc)
{
    const int idx = blockIdx.x * 256 + threadIdx.x;   // over B*ENC/4
    const int b = idx / (ENC / 4);
    const int e4 = idx - b * (ENC / 4);
    const float4* p = (const float4*)(enc + (size_t)b * P * ENC) + e4;
    float4 s = make_float4(0.f, 0.f, 0.f, 0.f);
    for (int pp = 0; pp < P; pp++) {
        const float4 v = p[(size_t)pp * (ENC / 4)];
        s.x += v.x; s.y += v.y; s.z += v.z; s.w += v.w;
    }
    const float r = 1.f / (float)P;
    s.x *= r; s.y *= r; s.z *= r; s.w *= r;
    ((float4*)g_mean)[idx] = s;
}

// ---------------- reduce dual h0/c0 partials ----------------
__global__ void reduce_hc_k(const float* __restrict__ bch, const float* __restrict__ bcc)
{
    const int idx = blockIdx.x * 256 + threadIdx.x;   // B*2H
    const int b = idx / (2 * H);
    const int n = idx - b * (2 * H);
    float s = (n < H) ? bch[n] : bcc[n - H];
    for (int ss = 0; ss < NS_HC; ss++) s += g_part[(size_t)(ss * 64 + b) * (2 * H) + n];
    if (n < H) g_h[b * H + n] = s;
    else       g_c[b * H + (n - H)] = s;
}

// ---------------- fused: att_h partial-reduce + scores + softmax ----------
__global__ void __launch_bounds__(256) scores_k(
    const float* __restrict__ bh, const float* __restrict__ Wa, const float* __restrict__ ba)
{
    __shared__ float sh_h[A_DIM];
    __shared__ float sh_w[A_DIM];
    __shared__ float sc[256];
    __shared__ float red[256];
    const int b = blockIdx.x;
    const int tid = threadIdx.x;
    for (int a = tid; a < A_DIM; a += 256) {
        float s = bh[a];
#pragma unroll
        for (int ss = 0; ss < NS_AG; ss++) s += g_part[(size_t)(ss * 64 + b) * A_DIM + a];
        sh_h[a] = s;
        sh_w[a] = Wa[a];
    }
    __syncthreads();
    const int w = tid >> 5, lane = tid & 31;
    for (int p = w; p < P; p += 8) {
        const float* row = g_att_enc + (size_t)(b * P + p) * A_DIM;
        float s = 0.f;
#pragma unroll 4
        for (int a = lane; a < A_DIM; a += 32) {
            const float v = row[a] + sh_h[a];
            s += fmaxf(v, 0.f) * sh_w[a];
        }
#pragma unroll
        for (int off = 16; off; off >>= 1) s += __shfl_xor_sync(0xffffffff, s, off);
        if (lane == 0) sc[p] = s + ba[0];
    }
    __syncthreads();
    const float v = (tid < P) ? sc[tid] : -FLT_MAX;
    red[tid] = v;
    __syncthreads();
    for (int off = 128; off; off >>= 1) { if (tid < off) red[tid] = fmaxf(red[tid], red[tid + off]); __syncthreads(); }
    const float mx = red[0];
    __syncthreads();
    const float e = (tid < P) ? expf(v - mx) : 0.f;
    red[tid] = e;
    __syncthreads();
    for (int off = 128; off; off >>= 1) { if (tid < off) red[tid] += red[tid + off]; __syncthreads(); }
    const float inv = 1.f / red[0];
    if (tid < P) g_alpha[b * P + tid] = e * inv;
}

// =====================================================================
// mkinp: merged weighted-sum + gate-reduce + inp build + emb gather.
// =====================================================================
__global__ void __launch_bounds__(256) mkinp_k(
    const float* __restrict__ enc,
    const float* __restrict__ emb, const int* __restrict__ cap,
    const float* __restrict__ bg, int t)
{
    __shared__ float sa[P];
    const int idx = blockIdx.x * 256 + threadIdx.x;
    const int b = idx / (E + ENC);
    const int j = idx - b * (E + ENC);

    if (threadIdx.x < P) sa[threadIdx.x] = g_alpha[b * P + threadIdx.x];
    __syncthreads();

    if (j < E) {
        const int tok = cap[b * T + t];
        g_inp[idx] = emb[(size_t)tok * E + j];
    } else {
        const int ee = j - E;
        const float* col = enc + (size_t)b * P * ENC + ee;
        float s = 0.f;
#pragma unroll 4
        for (int p = 0; p < P; p++) s += sa[p] * col[(size_t)p * ENC];
        float g = bg[ee];
#pragma unroll
        for (int ss = 0; ss < NS_AG; ss++) g += g_part[GATE_OFF + (size_t)(ss * 64 + b) * ENC + ee];
        g_inp[idx] = s * g;
    }
}

// ---------------- LSTM cell (also appends h_t to g_hsave) ------------------
__global__ void lstm_k(const float* __restrict__ b_ih, const float* __restrict__ b_hh, int t)
{
    const int idx = blockIdx.x * 256 + threadIdx.x;
    const int b = idx >> 9;
    const int n = idx & (H - 1);
    float gv[4];
#pragma unroll
    for (int q = 0; q < 4; q++) {
        const int pos = q * H + n;
        float s = b_ih[pos] + b_hh[pos];
#pragma unroll
        for (int ss = 0; ss < NS_GATES; ss++) s += g_part[(size_t)(ss * 64 + b) * (4 * H) + pos];
        gv[q] = s;
    }
    const float i_ = sigm(gv[0]);
    const float f_ = sigm(gv[1]);
    const float gg = tanhf(gv[2]);
    const float o_ = sigm(gv[3]);
    const float c  = f_ * g_c[idx] + i_ * gg;
    g_c[idx] = c;
    const float hv = o_ * tanhf(c);
    g_h[idx] = hv;
    g_hsave[(size_t)t * (B * H) + idx] = hv;
}

// ---------------- zero the final time step ----------------
__global__ void zero_k(float* __restrict__ out)
{
    const int idx = blockIdx.x * 256 + threadIdx.x;
    if (idx < B * V) {
        const int b = idx / V;
        const int n = idx - b * V;
        out[(size_t)b * T * V + (size_t)(T - 1) * V + n] = 0.f;
    }
}

// ---------------- launch ----------------
extern "C" void kernel_launch(void* const* d_in, const int* in_sizes, int n_in,
                              void* d_out, int out_size)
{
    const float* enc  = (const float*)d_in[0];
    const int*   cap  = (const int*)d_in[1];
    const float* emb  = (const float*)d_in[2];
    const float* W_ih = (const float*)d_in[3];
    const float* b_ih = (const float*)d_in[4];
    const float* W_hh = (const float*)d_in[5];
    const float* b_hh = (const float*)d_in[6];
    const float* We   = (const float*)d_in[7];
    const float* be   = (const float*)d_in[8];
    const float* Wh   = (const float*)d_in[9];
    const float* bh   = (const float*)d_in[10];
    const float* Wa   = (const float*)d_in[11];
    const float* ba   = (const float*)d_in[12];
    const float* Wch  = (const float*)d_in[13];
    const float* bch  = (const float*)d_in[14];
    const float* Wcc  = (const float*)d_in[15];
    const float* bcc  = (const float*)d_in[16];
    const float* Wfc  = (const float*)d_in[17];
    const float* bfc  = (const float*)d_in[18];
    const float* Wg   = (const float*)d_in[19];
    const float* bg   = (const float*)d_in[20];
    float* out = (float*)d_out;

    float *p_att_enc, *p_part, *p_mean, *p_h, *p_c, *p_inp;
    cudaGetSymbolAddress((void**)&p_att_enc, g_att_enc);
    cudaGetSymbolAddress((void**)&p_part,    g_part);
    cudaGetSymbolAddress((void**)&p_mean,    g_mean);
    cudaGetSymbolAddress((void**)&p_h,       g_h);
    cudaGetSymbolAddress((void**)&p_c,       g_c);
    cudaGetSymbolAddress((void**)&p_inp,     g_inp);

    // ---- setup ----
    mean_k<<<(B * ENC / 4) / 256, 256>>>(enc);
    // h0 AND c0 in one dual-weight GEMM (grid 16 x 8), then one reduce
    gemm64_k<4><<<dim3(2 * H / 64, NS_HC), 128>>>(p_mean, ENC, nullptr, 0, Wch, ENC, Wcc, ENC, 0,
                                                  nullptr, p_part, 0, 0, ENC / NS_HC);
    reduce_hc_k<<<(B * 2 * H) / 256, 256>>>(bch, bcc);
    // att_enc = encode_out @ We^T + be   (grid 4 x 98, pipelined, conflict-free)
    gemm_big_k<<<dim3(A_DIM / 128, (B * P) / 128), 256>>>(enc, We, be, p_att_enc);

    // ---- recurrent loop: 5 launches per step ----
    for (int t = 0; t < T - 1; t++) {
        // att_h (h @ Wh^T) + gate (sigmoid(h) @ Wg^T) partials, split-K 8
        gemm64_k<3><<<dim3((A_DIM + ENC) / 64, NS_AG), 128>>>(
            p_h, H, nullptr, 0, Wh, H, Wg, H, 0, nullptr, p_part, 0, 0, H / NS_AG);
        // att_h reduce + scores + softmax -> alpha
        scores_k<<<B, 256>>>(bh, Wa, ba);
        // weighted + gate + inp build + emb gather
        mkinp_k<<<(B * (E + ENC)) / 256, 256>>>(enc, emb, cap, bg, t);
        // gates partials: dual-region K=3072, split-K 12 (chunk 256)
        gemm64_k<2><<<dim3((4 * H) / 64, NS_GATES), 128>>>(p_inp, E + ENC, p_h, H,
                                                           W_ih, E + ENC, W_hh, H, E + ENC,
                                                           nullptr, p_part, 4 * H, 4 * H, 256);
        lstm_k<<<(B * H) / 256, 256>>>(b_ih, b_hh, t);
    }

    // ---- ONE batched vocab projection for all 19 steps ----
    pred_big_k<<<dim3((V + 127) / 128, MSAVE / 128), 256>>>(Wfc, bfc, out);

    // out[:, T-1, :] = 0
    zero_k<<<(B * V + 255) / 256, 256>>>(out);
}

// round 16
// speedup vs baseline: 1.1221x; 1.0336x over previous
#include <cuda_runtime.h>
#include <math.h>
#include <float.h>

#define B    64
#define P    196
#define ENC  2048
#define H    512
#define E    512
#define A_DIM 512
#define V    30000
#define T    20

#define NS_HC    8   // h0/c0 split-K (chunk 256 over K=2048)
#define NS_AG    8   // combined att_h+gate split-K (chunk 64 over K=512)
#define NS_GATES 12  // gates split-K (chunk 256 over K=3072)
#define GATE_OFF (NS_AG * B * A_DIM)   // gate partials region in g_part
#define MSAVE    1280                  // padded rows for batched pred ( >= 19*64 )

// ---------------- scratch (device globals, no allocations) ----------------
__device__ __align__(128) float g_att_enc[B * P * A_DIM];
__device__ __align__(128) float g_part[NS_GATES * B * 4 * H];
__device__ __align__(128) float g_mean[B * ENC];
__device__ __align__(128) float g_h[B * H];
__device__ __align__(128) float g_c[B * H];
__device__ __align__(128) float g_alpha[B * P];
__device__ __align__(128) float g_inp[B * (E + ENC)];
__device__ __align__(128) float g_hsave[MSAVE * H];   // h_t stacked, row = t*64+b

__device__ __forceinline__ float sigm(float x) { return 1.f / (1.f + expf(-x)); }

// =====================================================================
// gemm64: C(part)[M=64, Ntile=64], 128 thr, 8x4 microtile, BK=16,
// register-prefetch pipelined.
// MODE 0 plain, 2 dual-region K, 3 combined att_h+gate, 4 combined h0/c0.
// =====================================================================
template <int MODE>
__global__ void __launch_bounds__(128) gemm64_k(
    const float* __restrict__ A1, int lda1,
    const float* __restrict__ A2, int lda2,
    const float* __restrict__ W1, int ldw1,
    const float* __restrict__ W2, int ldw2, int K1,
    const float* __restrict__ bias,
    float* __restrict__ C, long long ldc, int N, int kchunk)
{
    __shared__ float As[16][64];
    __shared__ float Ws[16][64];
    const int tid = threadIdx.x;
    const int s   = blockIdx.y;
    const int k0b = s * kchunk;

    const float* Abase; int ldA;
    const float* Wbase; int ldW;
    float* Cb; long long ldcl; int Nloc;
    bool sigA = false;
    int n0;

    if (MODE == 3) {
        const bool isg = blockIdx.x >= (A_DIM / 64);
        sigA = isg;
        Nloc = isg ? ENC : A_DIM;
        Abase = A1 + k0b; ldA = lda1;
        Wbase = (isg ? W2 : W1) + k0b; ldW = ldw1;
        Cb = C + (isg ? (size_t)GATE_OFF + (size_t)s * 64 * ENC
                      : (size_t)s * 64 * A_DIM);
        ldcl = Nloc;
        n0 = (isg ? (blockIdx.x - A_DIM / 64) : blockIdx.x) * 64;
    } else if (MODE == 4) {
        const bool isc = blockIdx.x >= (H / 64);
        Nloc = H;
        Abase = A1 + k0b; ldA = lda1;
        Wbase = (isc ? W2 : W1) + k0b; ldW = ldw1;
        Cb = C + (size_t)s * 64 * (2 * H) + (isc ? H : 0);
        ldcl = 2 * H;
        n0 = (isc ? (blockIdx.x - H / 64) : blockIdx.x) * 64;
    } else {
        Nloc = N;
        if (MODE == 2 && k0b >= K1) { Abase = A2 + (k0b - K1); ldA = lda2; Wbase = W2 + (k0b - K1); ldW = ldw2; }
        else                        { Abase = A1 + k0b;        ldA = lda1; Wbase = W1 + k0b;        ldW = ldw1; }
        Cb = C + (size_t)s * 64 * ldc;
        ldcl = ldc;
        n0 = blockIdx.x * 64;
    }

    const int lr = tid & 63;
    const int lk = (tid >> 6) * 8;
    const int wrow = n0 + lr;
    const float* Ap = Abase + (size_t)lr * ldA + lk;
    const float* Wp = (wrow < Nloc) ? (Wbase + (size_t)wrow * ldW + lk) : nullptr;
    const int tx = tid & 15;
    const int ty = tid >> 4;

    float acc[8][4];
#pragma unroll
    for (int i = 0; i < 8; i++)
#pragma unroll
        for (int j = 0; j < 4; j++) acc[i][j] = 0.f;

    float4 a0 = *(const float4*)(Ap);
    float4 a1 = *(const float4*)(Ap + 4);
    float4 w0, w1;
    if (Wp) { w0 = *(const float4*)(Wp); w1 = *(const float4*)(Wp + 4); }
    else    { w0 = make_float4(0, 0, 0, 0); w1 = w0; }

    for (int kk0 = 0; kk0 < kchunk; kk0 += 16) {
        float4 sa0 = a0, sa1 = a1, sw0 = w0, sw1 = w1;
        if (MODE == 3 && sigA) {
            sa0.x = sigm(sa0.x); sa0.y = sigm(sa0.y); sa0.z = sigm(sa0.z); sa0.w = sigm(sa0.w);
            sa1.x = sigm(sa1.x); sa1.y = sigm(sa1.y); sa1.z = sigm(sa1.z); sa1.w = sigm(sa1.w);
        }
        __syncthreads();
        As[lk + 0][lr] = sa0.x; As[lk + 1][lr] = sa0.y; As[lk + 2][lr] = sa0.z; As[lk + 3][lr] = sa0.w;
        As[lk + 4][lr] = sa1.x; As[lk + 5][lr] = sa1.y; As[lk + 6][lr] = sa1.z; As[lk + 7][lr] = sa1.w;
        Ws[lk + 0][lr] = sw0.x; Ws[lk + 1][lr] = sw0.y; Ws[lk + 2][lr] = sw0.z; Ws[lk + 3][lr] = sw0.w;
        Ws[lk + 4][lr] = sw1.x; Ws[lk + 5][lr] = sw1.y; Ws[lk + 6][lr] = sw1.z; Ws[lk + 7][lr] = sw1.w;
        __syncthreads();

        if (kk0 + 16 < kchunk) {
            a0 = *(const float4*)(Ap + kk0 + 16);
            a1 = *(const float4*)(Ap + kk0 + 20);
            if (Wp) { w0 = *(const float4*)(Wp + kk0 + 16); w1 = *(const float4*)(Wp + kk0 + 20); }
        }

#pragma unroll
        for (int kk = 0; kk < 16; kk++) {
            float4 ra0 = *(const float4*)&As[kk][ty * 8];
            float4 ra1 = *(const float4*)&As[kk][ty * 8 + 4];
            float4 rw  = *(const float4*)&Ws[kk][tx * 4];
            acc[0][0] += ra0.x * rw.x; acc[0][1] += ra0.x * rw.y; acc[0][2] += ra0.x * rw.z; acc[0][3] += ra0.x * rw.w;
            acc[1][0] += ra0.y * rw.x; acc[1][1] += ra0.y * rw.y; acc[1][2] += ra0.y * rw.z; acc[1][3] += ra0.y * rw.w;
            acc[2][0] += ra0.z * rw.x; acc[2][1] += ra0.z * rw.y; acc[2][2] += ra0.z * rw.z; acc[2][3] += ra0.z * rw.w;
            acc[3][0] += ra0.w * rw.x; acc[3][1] += ra0.w * rw.y; acc[3][2] += ra0.w * rw.z; acc[3][3] += ra0.w * rw.w;
            acc[4][0] += ra1.x * rw.x; acc[4][1] += ra1.x * rw.y; acc[4][2] += ra1.x * rw.z; acc[4][3] += ra1.x * rw.w;
            acc[5][0] += ra1.y * rw.x; acc[5][1] += ra1.y * rw.y; acc[5][2] += ra1.y * rw.z; acc[5][3] += ra1.y * rw.w;
            acc[6][0] += ra1.z * rw.x; acc[6][1] += ra1.z * rw.y; acc[6][2] += ra1.z * rw.z; acc[6][3] += ra1.z * rw.w;
            acc[7][0] += ra1.w * rw.x; acc[7][1] += ra1.w * rw.y; acc[7][2] += ra1.w * rw.z; acc[7][3] += ra1.w * rw.w;
        }
    }

#pragma unroll
    for (int i = 0; i < 8; i++) {
        const int mm = ty * 8 + i;
        const int n  = n0 + tx * 4;
        if (n < Nloc) {
            float4 v = make_float4(acc[i][0], acc[i][1], acc[i][2], acc[i][3]);
            if (MODE == 0 && bias) {
                const float4 bv = *(const float4*)(bias + n);
                v.x += bv.x; v.y += bv.y; v.z += bv.z; v.w += bv.w;
            }
            *(float4*)(Cb + (size_t)mm * ldcl + n) = v;
        }
    }
}

// =====================================================================
// gemm_big: 128x128 tile, 256 thr, 8x8 microtile — att_enc.
// Conflict-free W reads + DOUBLE-BUFFERED smem (one sync per chunk).
// =====================================================================
__global__ void __launch_bounds__(256) gemm_big_k(
    const float* __restrict__ Am,
    const float* __restrict__ Wm,
    const float* __restrict__ bias,
    float* __restrict__ C)
{
    __shared__ float As[2][16][128];
    __shared__ float Ws[2][16][128];
    const int tid = threadIdx.x;
    const int n0 = blockIdx.x * 128;
    const int m0 = blockIdx.y * 128;
    const int lr = tid & 127;
    const int lk = (tid >> 7) * 8;
    const float* Ap = Am + (size_t)(m0 + lr) * ENC + lk;
    const float* Wp = Wm + (size_t)(n0 + lr) * ENC + lk;
    const int tx = tid & 15;
    const int ty = tid >> 4;

    float acc[8][8];
#pragma unroll
    for (int i = 0; i < 8; i++)
#pragma unroll
        for (int j = 0; j < 8; j++) acc[i][j] = 0.f;

    float4 a0 = *(const float4*)(Ap);
    float4 a1 = *(const float4*)(Ap + 4);
    float4 w0 = *(const float4*)(Wp);
    float4 w1 = *(const float4*)(Wp + 4);
    As[0][lk + 0][lr] = a0.x; As[0][lk + 1][lr] = a0.y; As[0][lk + 2][lr] = a0.z; As[0][lk + 3][lr] = a0.w;
    As[0][lk + 4][lr] = a1.x; As[0][lk + 5][lr] = a1.y; As[0][lk + 6][lr] = a1.z; As[0][lk + 7][lr] = a1.w;
    Ws[0][lk + 0][lr] = w0.x; Ws[0][lk + 1][lr] = w0.y; Ws[0][lk + 2][lr] = w0.z; Ws[0][lk + 3][lr] = w0.w;
    Ws[0][lk + 4][lr] = w1.x; Ws[0][lk + 5][lr] = w1.y; Ws[0][lk + 6][lr] = w1.z; Ws[0][lk + 7][lr] = w1.w;
    __syncthreads();

    constexpr int NCH = ENC / 16;
    for (int c = 0; c < NCH; c++) {
        const int sb = c & 1;
        const bool more = (c + 1 < NCH);
        if (more) {
            a0 = *(const float4*)(Ap + (c + 1) * 16);
            a1 = *(const float4*)(Ap + (c + 1) * 16 + 4);
            w0 = *(const float4*)(Wp + (c + 1) * 16);
            w1 = *(const float4*)(Wp + (c + 1) * 16 + 4);
        }
#pragma unroll
        for (int kk = 0; kk < 16; kk++) {
            float4 ra0 = *(const float4*)&As[sb][kk][ty * 8];
            float4 ra1 = *(const float4*)&As[sb][kk][ty * 8 + 4];
            float4 rw0 = *(const float4*)&Ws[sb][kk][tx * 4];
            float4 rw1 = *(const float4*)&Ws[sb][kk][64 + tx * 4];
            const float aval[8] = {ra0.x, ra0.y, ra0.z, ra0.w, ra1.x, ra1.y, ra1.z, ra1.w};
            const float wval[8] = {rw0.x, rw0.y, rw0.z, rw0.w, rw1.x, rw1.y, rw1.z, rw1.w};
#pragma unroll
            for (int i = 0; i < 8; i++)
#pragma unroll
                for (int j = 0; j < 8; j++) acc[i][j] += aval[i] * wval[j];
        }
        if (more) {
            const int sn = sb ^ 1;
            As[sn][lk + 0][lr] = a0.x; As[sn][lk + 1][lr] = a0.y; As[sn][lk + 2][lr] = a0.z; As[sn][lk + 3][lr] = a0.w;
            As[sn][lk + 4][lr] = a1.x; As[sn][lk + 5][lr] = a1.y; As[sn][lk + 6][lr] = a1.z; As[sn][lk + 7][lr] = a1.w;
            Ws[sn][lk + 0][lr] = w0.x; Ws[sn][lk + 1][lr] = w0.y; Ws[sn][lk + 2][lr] = w0.z; Ws[sn][lk + 3][lr] = w0.w;
            Ws[sn][lk + 4][lr] = w1.x; Ws[sn][lk + 5][lr] = w1.y; Ws[sn][lk + 6][lr] = w1.z; Ws[sn][lk + 7][lr] = w1.w;
            __syncthreads();
        }
    }

#pragma unroll
    for (int i = 0; i < 8; i++) {
        const int m = m0 + ty * 8 + i;
#pragma unroll
        for (int jj = 0; jj < 2; jj++) {
            const int n = n0 + jj * 64 + tx * 4;
            const float4 bv = *(const float4*)(bias + n);
            float4 v = make_float4(acc[i][jj*4+0] + bv.x, acc[i][jj*4+1] + bv.y,
                                   acc[i][jj*4+2] + bv.z, acc[i][jj*4+3] + bv.w);
            *(float4*)(C + (size_t)m * A_DIM + n) = v;
        }
    }
}

// =====================================================================
// pred_big: batched vocab projection — conflict-free + double-buffered.
// =====================================================================
__global__ void __launch_bounds__(256) pred_big_k(
    const float* __restrict__ Wfc,
    const float* __restrict__ bfc,
    float* __restrict__ out)
{
    __shared__ float As[2][16][128];
    __shared__ float Ws[2][16][128];
    const int tid = threadIdx.x;
    const int n0 = blockIdx.x * 128;
    const int m0 = blockIdx.y * 128;
    const int lr = tid & 127;
    const int lk = (tid >> 7) * 8;
    const float* Ap = g_hsave + (size_t)(m0 + lr) * H + lk;
    const int wr = min(n0 + lr, V - 1);
    const float* Wp = Wfc + (size_t)wr * H + lk;
    const int tx = tid & 15;
    const int ty = tid >> 4;

    float acc[8][8];
#pragma unroll
    for (int i = 0; i < 8; i++)
#pragma unroll
        for (int j = 0; j < 8; j++) acc[i][j] = 0.f;

    float4 a0 = *(const float4*)(Ap);
    float4 a1 = *(const float4*)(Ap + 4);
    float4 w0 = *(const float4*)(Wp);
    float4 w1 = *(const float4*)(Wp + 4);
    As[0][lk + 0][lr] = a0.x; As[0][lk + 1][lr] = a0.y; As[0][lk + 2][lr] = a0.z; As[0][lk + 3][lr] = a0.w;
    As[0][lk + 4][lr] = a1.x; As[0][lk + 5][lr] = a1.y; As[0][lk + 6][lr] = a1.z; As[0][lk + 7][lr] = a1.w;
    Ws[0][lk + 0][lr] = w0.x; Ws[0][lk + 1][lr] = w0.y; Ws[0][lk + 2][lr] = w0.z; Ws[0][lk + 3][lr] = w0.w;
    Ws[0][lk + 4][lr] = w1.x; Ws[0][lk + 5][lr] = w1.y; Ws[0][lk + 6][lr] = w1.z; Ws[0][lk + 7][lr] = w1.w;
    __syncthreads();

    constexpr int NCH = H / 16;
    for (int c = 0; c < NCH; c++) {
        const int sb = c & 1;
        const bool more = (c + 1 < NCH);
        if (more) {
            a0 = *(const float4*)(Ap + (c + 1) * 16);
            a1 = *(const float4*)(Ap + (c + 1) * 16 + 4);
            w0 = *(const float4*)(Wp + (c + 1) * 16);
            w1 = *(const float4*)(Wp + (c + 1) * 16 + 4);
        }
#pragma unroll
        for (int kk = 0; kk < 16; kk++) {
            float4 ra0 = *(const float4*)&As[sb][kk][ty * 8];
            float4 ra1 = *(const float4*)&As[sb][kk][ty * 8 + 4];
            float4 rw0 = *(const float4*)&Ws[sb][kk][tx * 4];
            float4 rw1 = *(const float4*)&Ws[sb][kk][64 + tx * 4];
            const float aval[8] = {ra0.x, ra0.y, ra0.z, ra0.w, ra1.x, ra1.y, ra1.z, ra1.w};
            const float wval[8] = {rw0.x, rw0.y, rw0.z, rw0.w, rw1.x, rw1.y, rw1.z, rw1.w};
#pragma unroll
            for (int i = 0; i < 8; i++)
#pragma unroll
                for (int j = 0; j < 8; j++) acc[i][j] += aval[i] * wval[j];
        }
        if (more) {
            const int sn = sb ^ 1;
            As[sn][lk + 0][lr] = a0.x; As[sn][lk + 1][lr] = a0.y; As[sn][lk + 2][lr] = a0.z; As[sn][lk + 3][lr] = a0.w;
            As[sn][lk + 4][lr] = a1.x; As[sn][lk + 5][lr] = a1.y; As[sn][lk + 6][lr] = a1.z; As[sn][lk + 7][lr] = a1.w;
            Ws[sn][lk + 0][lr] = w0.x; Ws[sn][lk + 1][lr] = w0.y; Ws[sn][lk + 2][lr] = w0.z; Ws[sn][lk + 3][lr] = w0.w;
            Ws[sn][lk + 4][lr] = w1.x; Ws[sn][lk + 5][lr] = w1.y; Ws[sn][lk + 6][lr] = w1.z; Ws[sn][lk + 7][lr] = w1.w;
            __syncthreads();
        }
    }

#pragma unroll
    for (int i = 0; i < 8; i++) {
        const int r = m0 + ty * 8 + i;              // = t*64 + b
        if (r < (T - 1) * B) {
            const int t = r >> 6;
            const int b = r & 63;
            float* orow = out + (size_t)b * T * V + (size_t)t * V;
#pragma unroll
            for (int jj = 0; jj < 2; jj++) {
                const int n = n0 + jj * 64 + tx * 4;
                if (n < V) {                        // V % 4 == 0
                    const float4 bv = *(const float4*)(bfc + n);
                    float4 v = make_float4(acc[i][jj*4+0] + bv.x, acc[i][jj*4+1] + bv.y,
                                           acc[i][jj*4+2] + bv.z, acc[i][jj*4+3] + bv.w);
                    *(float4*)(orow + n) = v;
                }
            }
        }
    }
}

// ---------------- mean over P (float4 vectorized) ----------------
__global__ void mean_k(const float* __restrict__ enc)
{
    const int idx = blockIdx.x * 256 + threadIdx.x;   // over B*ENC/4
    const int b = idx / (ENC / 4);
    const int e4 = idx - b * (ENC / 4);
    const float4* p = (const float4*)(enc + (size_t)b * P * ENC) + e4;
    float4 s = make_float4(0.f, 0.f, 0.f, 0.f);
    for (int pp = 0; pp < P; pp++) {
        const float4 v = p[(size_t)pp * (ENC / 4)];
        s.x += v.x; s.y += v.y; s.z += v.z; s.w += v.w;
    }
    const float r = 1.f / (float)P;
    s.x *= r; s.y *= r; s.z *= r; s.w *= r;
    ((float4*)g_mean)[idx] = s;
}

// ---------------- reduce dual h0/c0 partials ----------------
__global__ void reduce_hc_k(const float* __restrict__ bch, const float* __restrict__ bcc)
{
    const int idx = blockIdx.x * 256 + threadIdx.x;   // B*2H
    const int b = idx / (2 * H);
    const int n = idx - b * (2 * H);
    float s = (n < H) ? bch[n] : bcc[n - H];
    for (int ss = 0; ss < NS_HC; ss++) s += g_part[(size_t)(ss * 64 + b) * (2 * H) + n];
    if (n < H) g_h[b * H + n] = s;
    else       g_c[b * H + (n - H)] = s;
}

// ---------------- fused: att_h partial-reduce + scores + softmax ----------
__global__ void __launch_bounds__(256) scores_k(
    const float* __restrict__ bh, const float* __restrict__ Wa, const float* __restrict__ ba)
{
    __shared__ float sh_h[A_DIM];
    __shared__ float sh_w[A_DIM];
    __shared__ float sc[256];
    __shared__ float red[256];
    const int b = blockIdx.x;
    const int tid = threadIdx.x;
    for (int a = tid; a < A_DIM; a += 256) {
        float s = bh[a];
#pragma unroll
        for (int ss = 0; ss < NS_AG; ss++) s += g_part[(size_t)(ss * 64 + b) * A_DIM + a];
        sh_h[a] = s;
        sh_w[a] = Wa[a];
    }
    __syncthreads();
    const int w = tid >> 5, lane = tid & 31;
    for (int p = w; p < P; p += 8) {
        const float* row = g_att_enc + (size_t)(b * P + p) * A_DIM;
        float s = 0.f;
#pragma unroll 4
        for (int a = lane; a < A_DIM; a += 32) {
            const float v = row[a] + sh_h[a];
            s += fmaxf(v, 0.f) * sh_w[a];
        }
#pragma unroll
        for (int off = 16; off; off >>= 1) s += __shfl_xor_sync(0xffffffff, s, off);
        if (lane == 0) sc[p] = s + ba[0];
    }
    __syncthreads();
    const float v = (tid < P) ? sc[tid] : -FLT_MAX;
    red[tid] = v;
    __syncthreads();
    for (int off = 128; off; off >>= 1) { if (tid < off) red[tid] = fmaxf(red[tid], red[tid + off]); __syncthreads(); }
    const float mx = red[0];
    __syncthreads();
    const float e = (tid < P) ? expf(v - mx) : 0.f;
    red[tid] = e;
    __syncthreads();
    for (int off = 128; off; off >>= 1) { if (tid < off) red[tid] += red[tid + off]; __syncthreads(); }
    const float inv = 1.f / red[0];
    if (tid < P) g_alpha[b * P + tid] = e * inv;
}

// =====================================================================
// mkinp: merged weighted-sum + gate-reduce + inp build + emb gather.
// =====================================================================
__global__ void __launch_bounds__(256) mkinp_k(
    const float* __restrict__ enc,
    const float* __restrict__ emb, const int* __restrict__ cap,
    const float* __restrict__ bg, int t)
{
    __shared__ float sa[P];
    const int idx = blockIdx.x * 256 + threadIdx.x;
    const int b = idx / (E + ENC);
    const int j = idx - b * (E + ENC);

    if (threadIdx.x < P) sa[threadIdx.x] = g_alpha[b * P + threadIdx.x];
    __syncthreads();

    if (j < E) {
        const int tok = cap[b * T + t];
        g_inp[idx] = emb[(size_t)tok * E + j];
    } else {
        const int ee = j - E;
        const float* col = enc + (size_t)b * P * ENC + ee;
        float s = 0.f;
#pragma unroll 4
        for (int p = 0; p < P; p++) s += sa[p] * col[(size_t)p * ENC];
        float g = bg[ee];
#pragma unroll
        for (int ss = 0; ss < NS_AG; ss++) g += g_part[GATE_OFF + (size_t)(ss * 64 + b) * ENC + ee];
        g_inp[idx] = s * g;
    }
}

// ---------------- LSTM cell (also appends h_t to g_hsave) ------------------
__global__ void lstm_k(const float* __restrict__ b_ih, const float* __restrict__ b_hh, int t)
{
    const int idx = blockIdx.x * 256 + threadIdx.x;
    const int b = idx >> 9;
    const int n = idx & (H - 1);
    float gv[4];
#pragma unroll
    for (int q = 0; q < 4; q++) {
        const int pos = q * H + n;
        float s = b_ih[pos] + b_hh[pos];
#pragma unroll
        for (int ss = 0; ss < NS_GATES; ss++) s += g_part[(size_t)(ss * 64 + b) * (4 * H) + pos];
        gv[q] = s;
    }
    const float i_ = sigm(gv[0]);
    const float f_ = sigm(gv[1]);
    const float gg = tanhf(gv[2]);
    const float o_ = sigm(gv[3]);
    const float c  = f_ * g_c[idx] + i_ * gg;
    g_c[idx] = c;
    const float hv = o_ * tanhf(c);
    g_h[idx] = hv;
    g_hsave[(size_t)t * (B * H) + idx] = hv;
}

// ---------------- zero the final time step ----------------
__global__ void zero_k(float* __restrict__ out)
{
    const int idx = blockIdx.x * 256 + threadIdx.x;
    if (idx < B * V) {
        const int b = idx / V;
        const int n = idx - b * V;
        out[(size_t)b * T * V + (size_t)(T - 1) * V + n] = 0.f;
    }
}

// ---------------- launch ----------------
extern "C" void kernel_launch(void* const* d_in, const int* in_sizes, int n_in,
                              void* d_out, int out_size)
{
    const float* enc  = (const float*)d_in[0];
    const int*   cap  = (const int*)d_in[1];
    const float* emb  = (const float*)d_in[2];
    const float* W_ih = (const float*)d_in[3];
    const float* b_ih = (const float*)d_in[4];
    const float* W_hh = (const float*)d_in[5];
    const float* b_hh = (const float*)d_in[6];
    const float* We   = (const float*)d_in[7];
    const float* be   = (const float*)d_in[8];
    const float* Wh   = (const float*)d_in[9];
    const float* bh   = (const float*)d_in[10];
    const float* Wa   = (const float*)d_in[11];
    const float* ba   = (const float*)d_in[12];
    const float* Wch  = (const float*)d_in[13];
    const float* bch  = (const float*)d_in[14];
    const float* Wcc  = (const float*)d_in[15];
    const float* bcc  = (const float*)d_in[16];
    const float* Wfc  = (const float*)d_in[17];
    const float* bfc  = (const float*)d_in[18];
    const float* Wg   = (const float*)d_in[19];
    const float* bg   = (const float*)d_in[20];
    float* out = (float*)d_out;

    float *p_att_enc, *p_part, *p_mean, *p_h, *p_c, *p_inp;
    cudaGetSymbolAddress((void**)&p_att_enc, g_att_enc);
    cudaGetSymbolAddress((void**)&p_part,    g_part);
    cudaGetSymbolAddress((void**)&p_mean,    g_mean);
    cudaGetSymbolAddress((void**)&p_h,       g_h);
    cudaGetSymbolAddress((void**)&p_c,       g_c);
    cudaGetSymbolAddress((void**)&p_inp,     g_inp);

    // ---- setup ----
    mean_k<<<(B * ENC / 4) / 256, 256>>>(enc);
    gemm64_k<4><<<dim3(2 * H / 64, NS_HC), 128>>>(p_mean, ENC, nullptr, 0, Wch, ENC, Wcc, ENC, 0,
                                                  nullptr, p_part, 0, 0, ENC / NS_HC);
    reduce_hc_k<<<(B * 2 * H) / 256, 256>>>(bch, bcc);
    // att_enc = encode_out @ We^T + be   (grid 4 x 98, double-buffered)
    gemm_big_k<<<dim3(A_DIM / 128, (B * P) / 128), 256>>>(enc, We, be, p_att_enc);

    // ---- recurrent loop: 5 launches per step ----
    for (int t = 0; t < T - 1; t++) {
        gemm64_k<3><<<dim3((A_DIM + ENC) / 64, NS_AG), 128>>>(
            p_h, H, nullptr, 0, Wh, H, Wg, H, 0, nullptr, p_part, 0, 0, H / NS_AG);
        scores_k<<<B, 256>>>(bh, Wa, ba);
        mkinp_k<<<(B * (E + ENC)) / 256, 256>>>(enc, emb, cap, bg, t);
        gemm64_k<2><<<dim3((4 * H) / 64, NS_GATES), 128>>>(p_inp, E + ENC, p_h, H,
                                                           W_ih, E + ENC, W_hh, H, E + ENC,
                                                           nullptr, p_part, 4 * H, 4 * H, 256);
        lstm_k<<<(B * H) / 256, 256>>>(b_ih, b_hh, t);
    }

    // ---- ONE batched vocab projection for all 19 steps (double-buffered) ----
    pred_big_k<<<dim3((V + 127) / 128, MSAVE / 128), 256>>>(Wfc, bfc, out);

    // out[:, T-1, :] = 0
    zero_k<<<(B * V + 255) / 256, 256>>>(out);
}